// round 1
// baseline (speedup 1.0000x reference)
#include <cuda_runtime.h>
#include <cstdint>

// KANSplineLayer: out[b,o] = sum_i x[b,i]*W[o,i] + sum_i sum_g sigmoid(x[b,i]+grid[i,o,g])
//
// Spline restructuring: with u = exp(-x), a_g = exp(-grid):
//   sum_g sigmoid = sum_g 1/(1+a_g*u) = G - u*Q'(u)/Q(u),  Q(u)=prod_g(1+a_g*u)
// Q's coefficients depend only on (i,o) and are shared across all B=16 batch rows,
// reducing MUFU work from 2 per sigmoid to 1 rcp per (b,i,o) + shared-coefficient
// Horner. Q and N=-u*Q' are evaluated together with packed fma.rn.f32x2.

#define B_   16
#define IN_  1024
#define OUT_ 1024
#define G_   8
#define I_CHUNK 16
#define O_TILE  256

__device__ __forceinline__ unsigned long long pack2(float lo, float hi) {
    unsigned long long r;
    asm("mov.b64 %0, {%1, %2};" : "=l"(r)
        : "r"(__float_as_uint(lo)), "r"(__float_as_uint(hi)));
    return r;
}

// ---------------- Kernel 1: base GEMM, also initializes d_out ----------------
__global__ __launch_bounds__(128) void kan_base_kernel(
    const float* __restrict__ x, const float* __restrict__ w, float* __restrict__ out)
{
    const int o = blockIdx.x;
    const float* wrow = w + (size_t)o * IN_;
    float s[B_];
    #pragma unroll
    for (int b = 0; b < B_; b++) s[b] = 0.f;

    for (int i = threadIdx.x; i < IN_; i += 128) {
        float wv = wrow[i];                 // coalesced
        #pragma unroll
        for (int b = 0; b < B_; b++)
            s[b] = fmaf(x[b * IN_ + i], wv, s[b]);  // x cached (64KB total)
    }
    // intra-warp reduction
    #pragma unroll
    for (int b = 0; b < B_; b++) {
        #pragma unroll
        for (int off = 16; off; off >>= 1)
            s[b] += __shfl_down_sync(0xffffffffu, s[b], off);
    }
    __shared__ float red[4][B_];
    int wid = threadIdx.x >> 5, lid = threadIdx.x & 31;
    if (lid == 0) {
        #pragma unroll
        for (int b = 0; b < B_; b++) red[wid][b] = s[b];
    }
    __syncthreads();
    if (threadIdx.x < B_) {
        int b = threadIdx.x;
        out[b * OUT_ + o] = red[0][b] + red[1][b] + red[2][b] + red[3][b];
    }
}

// ---------------- Kernel 2: spline via rational Horner + atomic add ----------
__global__ __launch_bounds__(256) void kan_spline_kernel(
    const float* __restrict__ x, const float* __restrict__ grid, float* __restrict__ out)
{
    __shared__ float u_s[I_CHUNK * B_];     // u = exp(-x) for this i-chunk
    const int i0 = blockIdx.y * I_CHUNK;
    const int o  = blockIdx.x * O_TILE + threadIdx.x;

    {   // 256 threads == I_CHUNK*B_ exactly
        int t  = threadIdx.x;
        int il = t >> 4, b = t & 15;
        u_s[t] = __expf(-x[b * IN_ + (i0 + il)]);
    }
    __syncthreads();

    float acc[B_];
    #pragma unroll
    for (int b = 0; b < B_; b++) acc[b] = 0.f;

    for (int il = 0; il < I_CHUNK; il++) {
        const int i = i0 + il;
        const float4* gp =
            reinterpret_cast<const float4*>(grid + ((size_t)i * OUT_ + o) * G_);
        float4 g0 = gp[0], g1 = gp[1];      // 32B/lane, fully coalesced
        float a[8] = { __expf(-g0.x), __expf(-g0.y), __expf(-g0.z), __expf(-g0.w),
                       __expf(-g1.x), __expf(-g1.y), __expf(-g1.z), __expf(-g1.w) };

        // Build Q(u) = prod_g (1 + a_g u) coefficients q[0..8] (all positive).
        float q[9];
        q[0] = 1.f;
        #pragma unroll
        for (int g = 0; g < 8; g++) {
            q[g + 1] = a[g] * q[g];
            #pragma unroll
            for (int k = g; k >= 1; --k)
                q[k] = fmaf(a[g], q[k - 1], q[k]);
        }
        // Packed coeffs: lo = q_k (for Q), hi = -k*q_k (for N = -u*Q').
        unsigned long long c[9];
        #pragma unroll
        for (int k = 0; k <= 8; k++)
            c[k] = pack2(q[k], -(float)k * q[k]);

        #pragma unroll
        for (int b = 0; b < B_; b++) {
            float u = u_s[il * B_ + b];               // LDS broadcast
            unsigned long long u2 = pack2(u, u);
            unsigned long long h  = c[8];
            #pragma unroll
            for (int k = 7; k >= 0; --k)
                asm("fma.rn.f32x2 %0, %0, %1, %2;" : "+l"(h) : "l"(u2), "l"(c[k]));
            unsigned int lo_, hi_;
            asm("mov.b64 {%0, %1}, %2;" : "=r"(lo_), "=r"(hi_) : "l"(h));
            float Qv = __uint_as_float(lo_);
            float Nn = __uint_as_float(hi_);          // = -u*Q'(u)
            float r;
            asm("rcp.approx.f32 %0, %1;" : "=f"(r) : "f"(Qv));
            // sum_g sigmoid = G + Nn/Q ; the +G per i is folded into cst below.
            acc[b] = fmaf(Nn, r, acc[b]);
        }
    }

    const float cst = (float)(G_ * I_CHUNK);
    #pragma unroll
    for (int b = 0; b < B_; b++)
        atomicAdd(out + b * OUT_ + o, acc[b] + cst);
}

// ---------------- launch ----------------
extern "C" void kernel_launch(void* const* d_in, const int* in_sizes, int n_in,
                              void* d_out, int out_size)
{
    const float* x    = (const float*)d_in[0];   // [B, IN]
    const float* w    = (const float*)d_in[1];   // [OUT, IN]
    const float* grid = (const float*)d_in[2];   // [IN, OUT, G]
    float* out = (float*)d_out;                  // [B, OUT]

    kan_base_kernel<<<OUT_, 128>>>(x, w, out);   // writes/initializes all of out
    kan_spline_kernel<<<dim3(OUT_ / O_TILE, IN_ / I_CHUNK), 256>>>(x, grid, out);
}

// round 2
// speedup vs baseline: 1.0570x; 1.0570x over previous
#include <cuda_runtime.h>
#include <cstdint>

// KANSplineLayer fused: out[b,o] = sum_i x[b,i]*W[o,i] + sum_i sum_g sigmoid(x[b,i]+grid[i,o,g])
//
// Spline: with u=exp(-x), a_g=exp(-grid): sum_g sigmoid = G - u*Q'(u)/Q(u),
// Q(u)=prod_g(1+a_g*u). Coefficients of (Q, -uQ') depend only on (i,o), shared
// across all 16 batch rows; evaluated with packed fma.rn.f32x2 + one rcp per (b,i,o).
// Base GEMM fused into the same (i,o) loop using a pre-transposed W (coalesced).

#define B_   16
#define IN_  1024
#define OUT_ 1024
#define G_   8
#define I_CHUNK 8

__device__ float Wt_g[IN_ * OUT_];   // W^T scratch (4MB, static — no allocs)

__device__ __forceinline__ unsigned long long pack2(float lo, float hi) {
    unsigned long long r;
    asm("mov.b64 %0, {%1, %2};" : "=l"(r)
        : "r"(__float_as_uint(lo)), "r"(__float_as_uint(hi)));
    return r;
}

// ---------- Kernel 1: transpose W into Wt_g, zero-init out ----------
__global__ __launch_bounds__(256) void kan_prep_kernel(
    const float* __restrict__ w, float* __restrict__ out)
{
    __shared__ float tile[32][33];
    const int bx = blockIdx.x, by = blockIdx.y;       // 32 x 32 CTAs
    const int i0 = bx * 32, o0 = by * 32;
    #pragma unroll
    for (int r = threadIdx.y; r < 32; r += 8)
        tile[r][threadIdx.x] = w[(size_t)(o0 + r) * IN_ + (i0 + threadIdx.x)];
    __syncthreads();
    #pragma unroll
    for (int r = threadIdx.y; r < 32; r += 8)
        Wt_g[(size_t)(i0 + r) * OUT_ + (o0 + threadIdx.x)] = tile[threadIdx.x][r];

    const int cta = by * 32 + bx;                     // 0..1023
    if (cta < (B_ * OUT_) / 256) {                    // first 64 CTAs zero d_out
        out[cta * 256 + threadIdx.y * 32 + threadIdx.x] = 0.f;
    }
}

// ---------- Kernel 2: fused base + spline, atomic accumulate ----------
__global__ __launch_bounds__(256, 4) void kan_fused_kernel(
    const float* __restrict__ x, const float* __restrict__ grid,
    float* __restrict__ out)
{
    __shared__ float2 ux_s[I_CHUNK * B_];             // (u, x) per (il, b)
    const int i0 = blockIdx.y * I_CHUNK;
    const int o  = blockIdx.x * 256 + threadIdx.x;

    if (threadIdx.x < I_CHUNK * B_) {
        int il = threadIdx.x >> 4, b = threadIdx.x & 15;
        float xv = x[b * IN_ + (i0 + il)];
        ux_s[threadIdx.x] = make_float2(__expf(-xv), xv);
    }
    __syncthreads();

    float acc[B_];
    #pragma unroll
    for (int b = 0; b < B_; b++) acc[b] = 0.f;

    const float4* gp = reinterpret_cast<const float4*>(
        grid + ((size_t)i0 * OUT_ + o) * G_);
    const float* wp = Wt_g + (size_t)i0 * OUT_ + o;

    #pragma unroll 1
    for (int il = 0; il < I_CHUNK; il++) {
        float4 g0 = gp[0], g1 = gp[1];                // 32B/lane, coalesced
        gp += (OUT_ * G_) / 4;
        float wv = *wp;                               // coalesced (W^T)
        wp += OUT_;

        float a[8] = { __expf(-g0.x), __expf(-g0.y), __expf(-g0.z), __expf(-g0.w),
                       __expf(-g1.x), __expf(-g1.y), __expf(-g1.z), __expf(-g1.w) };

        // Q(u) = prod_g (1 + a_g u): all-positive coefficients q[0..8].
        float q[9];
        q[0] = 1.f;
        #pragma unroll
        for (int g = 0; g < 8; g++) {
            q[g + 1] = a[g] * q[g];
            #pragma unroll
            for (int k = g; k >= 1; --k)
                q[k] = fmaf(a[g], q[k - 1], q[k]);
        }
        // Packed: lo = q_k (Q), hi = -k*q_k (N = -u*Q').
        unsigned long long c[9];
        c[0] = pack2(1.f, 0.f);
        #pragma unroll
        for (int k = 1; k <= 8; k++)
            c[k] = pack2(q[k], -(float)k * q[k]);

        #pragma unroll
        for (int b = 0; b < B_; b++) {
            float2 ux = ux_s[il * B_ + b];            // one LDS.64 broadcast
            unsigned long long u2 = pack2(ux.x, ux.x);
            unsigned long long h  = c[8];
            #pragma unroll
            for (int k = 7; k >= 0; --k)
                asm("fma.rn.f32x2 %0, %0, %1, %2;" : "+l"(h) : "l"(u2), "l"(c[k]));
            unsigned int lo_, hi_;
            asm("mov.b64 {%0, %1}, %2;" : "=r"(lo_), "=r"(hi_) : "l"(h));
            float Qv = __uint_as_float(lo_);
            float Nn = __uint_as_float(hi_);          // = -u*Q'(u)
            float r;
            asm("rcp.approx.f32 %0, %1;" : "=f"(r) : "f"(Qv));
            acc[b] = fmaf(Nn, r, fmaf(ux.y, wv, acc[b]));   // spline + base
        }
    }

    const float cst = (float)(G_ * I_CHUNK);          // folded "+G per i" terms
    #pragma unroll
    for (int b = 0; b < B_; b++)
        atomicAdd(out + b * OUT_ + o, acc[b] + cst);
}

// ---------------- launch ----------------
extern "C" void kernel_launch(void* const* d_in, const int* in_sizes, int n_in,
                              void* d_out, int out_size)
{
    const float* x    = (const float*)d_in[0];   // [B, IN]
    const float* w    = (const float*)d_in[1];   // [OUT, IN]
    const float* grid = (const float*)d_in[2];   // [IN, OUT, G]
    float* out = (float*)d_out;                  // [B, OUT]

    kan_prep_kernel<<<dim3(32, 32), dim3(32, 8)>>>(w, out);
    kan_fused_kernel<<<dim3(OUT_ / 256, IN_ / I_CHUNK), 256>>>(x, grid, out);
}

// round 3
// speedup vs baseline: 1.0656x; 1.0082x over previous
#include <cuda_runtime.h>
#include <cstdint>

// KANSplineLayer: out[b,o] = sum_i x[b,i]*W[o,i] + sum_i sum_g sigmoid(x[b,i]+grid[i,o,g])
//
// Spline: with u=exp(-x), a_g=exp(-grid): sum_g sigmoid = G - u*Q'(u)/Q(u),
// Q(u)=prod_g(1+a_g*u). (Q, -uQ') coefficients depend only on (i,o), shared across
// all 16 batch rows; evaluated with packed fma.rn.f32x2 + one rcp per (b,i,o).
// Base GEMM is a separate cheap kernel that also initializes d_out.

#define B_   16
#define IN_  1024
#define OUT_ 1024
#define G_   8
#define I_CHUNK 2

__device__ __forceinline__ unsigned long long pack2(float lo, float hi) {
    unsigned long long r;
    asm("mov.b64 %0, {%1, %2};" : "=l"(r)
        : "r"(__float_as_uint(lo)), "r"(__float_as_uint(hi)));
    return r;
}

// ---------- Kernel 1: base GEMM, initializes all of d_out ----------
__global__ __launch_bounds__(256) void kan_base_kernel(
    const float* __restrict__ x, const float* __restrict__ w, float* __restrict__ out)
{
    const int o = blockIdx.x;
    const float* wrow = w + (size_t)o * IN_;
    float s[B_];
    #pragma unroll
    for (int b = 0; b < B_; b++) s[b] = 0.f;

    #pragma unroll
    for (int it = 0; it < IN_ / 256; it++) {
        int i = it * 256 + threadIdx.x;
        float wv = wrow[i];                              // coalesced
        #pragma unroll
        for (int b = 0; b < B_; b++)
            s[b] = fmaf(x[b * IN_ + i], wv, s[b]);       // x stays in L1/L2 (64KB)
    }
    #pragma unroll
    for (int b = 0; b < B_; b++) {
        #pragma unroll
        for (int off = 16; off; off >>= 1)
            s[b] += __shfl_down_sync(0xffffffffu, s[b], off);
    }
    __shared__ float red[8][B_];
    int wid = threadIdx.x >> 5, lid = threadIdx.x & 31;
    if (lid == 0) {
        #pragma unroll
        for (int b = 0; b < B_; b++) red[wid][b] = s[b];
    }
    __syncthreads();
    if (threadIdx.x < B_) {
        int b = threadIdx.x;
        float t = 0.f;
        #pragma unroll
        for (int wg = 0; wg < 8; wg++) t += red[wg][b];
        out[b * OUT_ + o] = t;                           // init + base
    }
}

// ---------- spline body for one i: coeffs once, 16 batch evals ----------
__device__ __forceinline__ void spline_i(
    float4 g0, float4 g1, const unsigned long long* __restrict__ u2p,
    float* __restrict__ acc, unsigned long long c0)
{
    float a[8] = { __expf(-g0.x), __expf(-g0.y), __expf(-g0.z), __expf(-g0.w),
                   __expf(-g1.x), __expf(-g1.y), __expf(-g1.z), __expf(-g1.w) };

    // Q(u) = prod_g (1 + a_g u): all-positive coefficients q[1..8].
    float q[9];
    q[0] = 1.f;
    #pragma unroll
    for (int g = 0; g < 8; g++) {
        q[g + 1] = a[g] * q[g];
        #pragma unroll
        for (int k = g; k >= 1; --k)
            q[k] = fmaf(a[g], q[k - 1], q[k]);
    }
    // Packed: lo = q_k (Q), hi = -k*q_k (N = -u*Q').
    unsigned long long c[9];
    c[0] = c0;
    #pragma unroll
    for (int k = 1; k <= 8; k++)
        c[k] = pack2(q[k], -(float)k * q[k]);

    #pragma unroll
    for (int b = 0; b < B_; b++) {
        unsigned long long u2 = u2p[b];                  // LDS.64 broadcast, pre-packed (u,u)
        unsigned long long h  = c[8];
        #pragma unroll
        for (int k = 7; k >= 0; --k)
            asm("fma.rn.f32x2 %0, %0, %1, %2;" : "+l"(h) : "l"(u2), "l"(c[k]));
        unsigned int lo_, hi_;
        asm("mov.b64 {%0, %1}, %2;" : "=r"(lo_), "=r"(hi_) : "l"(h));
        float r;
        asm("rcp.approx.f32 %0, %1;" : "=f"(r) : "f"(__uint_as_float(lo_)));
        acc[b] = fmaf(__uint_as_float(hi_), r, acc[b]);  // += N/Q
    }
}

// ---------- Kernel 2: spline, atomic accumulate ----------
__global__ __launch_bounds__(256, 3) void kan_spline_kernel(
    const float* __restrict__ x, const float* __restrict__ grid,
    float* __restrict__ out)
{
    __shared__ unsigned long long u2s[I_CHUNK * B_];     // (u,u) packed per (il,b)
    const int i0 = blockIdx.y * I_CHUNK;
    const int o  = blockIdx.x * 256 + threadIdx.x;

    if (threadIdx.x < I_CHUNK * B_) {
        int il = threadIdx.x >> 4, b = threadIdx.x & 15;
        float u = __expf(-x[b * IN_ + (i0 + il)]);
        unsigned int ub = __float_as_uint(u);
        u2s[threadIdx.x] = ((unsigned long long)ub << 32) | ub;
    }
    __syncthreads();

    // Front-batch both iterations' grid loads (MLP=4 LDG.128).
    const float4* gp = reinterpret_cast<const float4*>(
        grid + ((size_t)i0 * OUT_ + o) * G_);
    float4 gA0 = gp[0], gA1 = gp[1];
    float4 gB0 = gp[(OUT_ * G_) / 4], gB1 = gp[(OUT_ * G_) / 4 + 1];

    float acc[B_];
    #pragma unroll
    for (int b = 0; b < B_; b++) acc[b] = 0.f;

    const unsigned long long c0 = pack2(1.f, 0.f);
    spline_i(gA0, gA1, u2s,       acc, c0);
    spline_i(gB0, gB1, u2s + B_,  acc, c0);

    const float cst = (float)(G_ * I_CHUNK);             // folded "+G per i" terms
    #pragma unroll
    for (int b = 0; b < B_; b++)
        atomicAdd(out + b * OUT_ + o, acc[b] + cst);
}

// ---------------- launch ----------------
extern "C" void kernel_launch(void* const* d_in, const int* in_sizes, int n_in,
                              void* d_out, int out_size)
{
    const float* x    = (const float*)d_in[0];   // [B, IN]
    const float* w    = (const float*)d_in[1];   // [OUT, IN]
    const float* grid = (const float*)d_in[2];   // [IN, OUT, G]
    float* out = (float*)d_out;                  // [B, OUT]

    kan_base_kernel<<<OUT_, 256>>>(x, w, out);                       // writes all of out
    kan_spline_kernel<<<dim3(OUT_ / 256, IN_ / I_CHUNK), 256>>>(x, grid, out);
}